// round 1
// baseline (speedup 1.0000x reference)
#include <cuda_runtime.h>
#include <math.h>
#include <stdint.h>

// Problem dims (fixed by the dataset)
#define TT 2048
#define SS 2048
#define BB 16
#define DD 1024
#define KK2 2048  // 2*DD

// Scratch (device globals — no allocation allowed in kernel_launch)
__device__ float g_scores[(size_t)BB * TT * SS];  // 256 MiB
__device__ float g_mix[(size_t)BB * TT * DD];     // 128 MiB

// ---------------- f32x2 packed-FMA helpers (sm_100+ PTX) ----------------
__device__ __forceinline__ unsigned long long pack2(float lo, float hi) {
    unsigned long long r;
    asm("mov.b64 %0, {%1, %2};" : "=l"(r) : "f"(lo), "f"(hi));
    return r;
}
__device__ __forceinline__ void fma2(unsigned long long& d, unsigned long long a, unsigned long long b) {
    asm("fma.rn.f32x2 %0, %1, %2, %0;" : "+l"(d) : "l"(a), "l"(b));
}
__device__ __forceinline__ float2 unpack2(unsigned long long v) {
    float lo, hi;
    asm("mov.b64 {%0, %1}, %2;" : "=f"(lo), "=f"(hi) : "l"(v));
    return make_float2(lo, hi);
}

// ---------------- shared tile helpers ----------------
// Transposed stash: takes two float4 rows (row lrow and lrow+64, k-range lcol..lcol+3)
// and stores k-major into Sm[k][m].
__device__ __forceinline__ void stash_T(float (*Sm)[132], int lrow, int lcol, float4 v0, float4 v1) {
    Sm[lcol + 0][lrow] = v0.x;
    Sm[lcol + 1][lrow] = v0.y;
    Sm[lcol + 2][lrow] = v0.z;
    Sm[lcol + 3][lrow] = v0.w;
    Sm[lcol + 0][lrow + 64] = v1.x;
    Sm[lcol + 1][lrow + 64] = v1.y;
    Sm[lcol + 2][lrow + 64] = v1.z;
    Sm[lcol + 3][lrow + 64] = v1.w;
}

// 16-k inner product step on a 128x128 tile; each thread owns an 8x8 microtile
// held as 8x4 packed f32x2 accumulators.
__device__ __forceinline__ void tile_compute(const float (*As)[132], const float (*Bs)[132],
                                             int tx, int ty, unsigned long long acc[8][4]) {
#pragma unroll
    for (int k = 0; k < 16; k++) {
        float4 av0 = *(const float4*)&As[k][ty * 8];
        float4 av1 = *(const float4*)&As[k][ty * 8 + 4];
        const unsigned long long* bp = (const unsigned long long*)&Bs[k][tx * 8];
        unsigned long long b0 = bp[0], b1 = bp[1], b2 = bp[2], b3 = bp[3];
        float a[8] = {av0.x, av0.y, av0.z, av0.w, av1.x, av1.y, av1.z, av1.w};
#pragma unroll
        for (int i = 0; i < 8; i++) {
            unsigned long long a2 = pack2(a[i], a[i]);
            fma2(acc[i][0], a2, b0);
            fma2(acc[i][1], a2, b1);
            fma2(acc[i][2], a2, b2);
            fma2(acc[i][3], a2, b3);
        }
    }
}

// ================= GEMM 1: scores[b,t,s] = sum_d q[t,b,d] * c[s,b,d]  (NT) =================
__global__ __launch_bounds__(256) void gemm_qk(const float* __restrict__ Q, const float* __restrict__ C) {
    __shared__ float As[16][132];
    __shared__ float Bs[16][132];
    const int tid = threadIdx.x;
    const int s0 = blockIdx.x * 128;
    const int t0 = blockIdx.y * 128;
    const int bz = blockIdx.z;
    const int lrow = tid >> 2;            // 0..63
    const int lcol = (tid & 3) << 2;      // 0,4,8,12
    // q row t of batch bz: Q[(t*BB + bz)*DD + k], row stride BB*DD
    const float* A0 = Q + ((size_t)(t0 + lrow) * BB + bz) * DD + lcol;
    const float* A1 = A0 + (size_t)64 * BB * DD;
    const float* B0 = C + ((size_t)(s0 + lrow) * BB + bz) * DD + lcol;
    const float* B1 = B0 + (size_t)64 * BB * DD;
    const int tx = tid & 15, ty = tid >> 4;

    unsigned long long acc[8][4];
#pragma unroll
    for (int i = 0; i < 8; i++)
#pragma unroll
        for (int j = 0; j < 4; j++) acc[i][j] = 0ull;

    for (int k0 = 0; k0 < DD; k0 += 16) {
        float4 a0 = *(const float4*)(A0 + k0);
        float4 a1 = *(const float4*)(A1 + k0);
        float4 b0 = *(const float4*)(B0 + k0);
        float4 b1 = *(const float4*)(B1 + k0);
        __syncthreads();
        stash_T(As, lrow, lcol, a0, a1);
        stash_T(Bs, lrow, lcol, b0, b1);
        __syncthreads();
        tile_compute(As, Bs, tx, ty, acc);
    }

    float* Cp = g_scores + ((size_t)bz * TT + t0 + ty * 8) * SS + s0 + tx * 8;
#pragma unroll
    for (int i = 0; i < 8; i++) {
        float2 p0 = unpack2(acc[i][0]), p1 = unpack2(acc[i][1]);
        float2 p2 = unpack2(acc[i][2]), p3 = unpack2(acc[i][3]);
        *(float4*)(Cp + (size_t)i * SS) = make_float4(p0.x, p0.y, p1.x, p1.y);
        *(float4*)(Cp + (size_t)i * SS + 4) = make_float4(p2.x, p2.y, p3.x, p3.y);
    }
}

// ================= softmax with ==0 -> -inf mask, in place on g_scores =================
__global__ __launch_bounds__(256) void softmax_mask() {
    float* p = g_scores + (size_t)blockIdx.x * SS;
    const int tid = threadIdx.x;
    __shared__ float red[256];
    float v[8];
    float m = -INFINITY;
#pragma unroll
    for (int i = 0; i < 8; i++) {
        v[i] = p[tid + i * 256];
        float x = (v[i] == 0.0f) ? -INFINITY : v[i];
        m = fmaxf(m, x);
    }
    red[tid] = m;
    __syncthreads();
#pragma unroll
    for (int s = 128; s > 0; s >>= 1) {
        if (tid < s) red[tid] = fmaxf(red[tid], red[tid + s]);
        __syncthreads();
    }
    m = red[0];
    __syncthreads();
    float e[8];
    float sum = 0.0f;
#pragma unroll
    for (int i = 0; i < 8; i++) {
        e[i] = (v[i] == 0.0f) ? 0.0f : __expf(v[i] - m);
        sum += e[i];
    }
    red[tid] = sum;
    __syncthreads();
#pragma unroll
    for (int s = 128; s > 0; s >>= 1) {
        if (tid < s) red[tid] += red[tid + s];
        __syncthreads();
    }
    float inv = 1.0f / red[0];
#pragma unroll
    for (int i = 0; i < 8; i++) p[tid + i * 256] = e[i] * inv;
}

// ================= GEMM 2: mix[b,t,d] = sum_s P[b,t,s] * c[s,b,d]  (NN) =================
__global__ __launch_bounds__(256) void gemm_pv(const float* __restrict__ C) {
    __shared__ float As[16][132];
    __shared__ float Bs[16][132];
    const int tid = threadIdx.x;
    const int n0 = blockIdx.x * 128;  // d
    const int t0 = blockIdx.y * 128;
    const int bz = blockIdx.z;
    const int lrow = tid >> 2;
    const int lcol = (tid & 3) << 2;
    const float* A0 = g_scores + ((size_t)bz * TT + t0 + lrow) * SS + lcol;
    const float* A1 = A0 + (size_t)64 * SS;
    const int brow = tid >> 4;        // 0..15 (k within tile)
    const int bc = (tid & 15) << 2;   // 0..60 (n within tile, float4)
    const float* Bbase = C + (size_t)bz * DD + n0 + bc;  // + k*(BB*DD)
    const int tx = tid & 15, ty = tid >> 4;

    unsigned long long acc[8][4];
#pragma unroll
    for (int i = 0; i < 8; i++)
#pragma unroll
        for (int j = 0; j < 4; j++) acc[i][j] = 0ull;

    for (int k0 = 0; k0 < SS; k0 += 16) {
        float4 a0 = *(const float4*)(A0 + k0);
        float4 a1 = *(const float4*)(A1 + k0);
        const float* bp = Bbase + (size_t)(k0 + brow) * (BB * DD);
        float4 b0 = *(const float4*)(bp);
        float4 b1 = *(const float4*)(bp + 64);
        __syncthreads();
        stash_T(As, lrow, lcol, a0, a1);
        *(float4*)&Bs[brow][bc] = b0;
        *(float4*)&Bs[brow][bc + 64] = b1;
        __syncthreads();
        tile_compute(As, Bs, tx, ty, acc);
    }

    float* Cp = g_mix + ((size_t)bz * TT + t0 + ty * 8) * DD + n0 + tx * 8;
#pragma unroll
    for (int i = 0; i < 8; i++) {
        float2 p0 = unpack2(acc[i][0]), p1 = unpack2(acc[i][1]);
        float2 p2 = unpack2(acc[i][2]), p3 = unpack2(acc[i][3]);
        *(float4*)(Cp + (size_t)i * DD) = make_float4(p0.x, p0.y, p1.x, p1.y);
        *(float4*)(Cp + (size_t)i * DD + 4) = make_float4(p2.x, p2.y, p3.x, p3.y);
    }
}

// ====== GEMM 3: out[b,t,d] = tanh( sum_k [mix|q][b,t,k] * W[d,k] + bias[d] )  (NT) ======
__global__ __launch_bounds__(256) void gemm_out(const float* __restrict__ Q, const float* __restrict__ W,
                                                const float* __restrict__ bias, float* __restrict__ out) {
    __shared__ float As[16][132];
    __shared__ float Bs[16][132];
    const int tid = threadIdx.x;
    const int n0 = blockIdx.x * 128;  // d
    const int t0 = blockIdx.y * 128;
    const int bz = blockIdx.z;
    const int lrow = tid >> 2;
    const int lcol = (tid & 3) << 2;
    // combined row t: k<DD -> mix[b,t,k]; k>=DD -> q[t,b,k-DD]
    const float* Am0 = g_mix + ((size_t)bz * TT + t0 + lrow) * DD + lcol;
    const float* Am1 = Am0 + (size_t)64 * DD;
    const float* Aq0 = Q + ((size_t)(t0 + lrow) * BB + bz) * DD + lcol - DD;  // so +k0 works for k0>=DD
    const float* Aq1 = Aq0 + (size_t)64 * BB * DD;
    const float* B0 = W + (size_t)(n0 + lrow) * KK2 + lcol;
    const float* B1 = B0 + (size_t)64 * KK2;
    const int tx = tid & 15, ty = tid >> 4;

    unsigned long long acc[8][4];
#pragma unroll
    for (int i = 0; i < 8; i++)
#pragma unroll
        for (int j = 0; j < 4; j++) acc[i][j] = 0ull;

    for (int k0 = 0; k0 < KK2; k0 += 16) {
        const float* a0p = (k0 < DD) ? (Am0 + k0) : (Aq0 + k0);
        const float* a1p = (k0 < DD) ? (Am1 + k0) : (Aq1 + k0);
        float4 a0 = *(const float4*)a0p;
        float4 a1 = *(const float4*)a1p;
        float4 b0 = *(const float4*)(B0 + k0);
        float4 b1 = *(const float4*)(B1 + k0);
        __syncthreads();
        stash_T(As, lrow, lcol, a0, a1);
        stash_T(Bs, lrow, lcol, b0, b1);
        __syncthreads();
        tile_compute(As, Bs, tx, ty, acc);
    }

    float bv[8];
#pragma unroll
    for (int j = 0; j < 8; j++) bv[j] = bias[n0 + tx * 8 + j];

    float* Cp = out + ((size_t)bz * TT + t0 + ty * 8) * DD + n0 + tx * 8;
#pragma unroll
    for (int i = 0; i < 8; i++) {
        float2 p0 = unpack2(acc[i][0]), p1 = unpack2(acc[i][1]);
        float2 p2 = unpack2(acc[i][2]), p3 = unpack2(acc[i][3]);
        float4 o0 = make_float4(tanhf(p0.x + bv[0]), tanhf(p0.y + bv[1]),
                                tanhf(p1.x + bv[2]), tanhf(p1.y + bv[3]));
        float4 o1 = make_float4(tanhf(p2.x + bv[4]), tanhf(p2.y + bv[5]),
                                tanhf(p3.x + bv[6]), tanhf(p3.y + bv[7]));
        *(float4*)(Cp + (size_t)i * DD) = o0;
        *(float4*)(Cp + (size_t)i * DD + 4) = o1;
    }
}

extern "C" void kernel_launch(void* const* d_in, const int* in_sizes, int n_in,
                              void* d_out, int out_size) {
    (void)in_sizes; (void)n_in; (void)out_size;
    const float* Q = (const float*)d_in[0];     // output [T,B,D]
    const float* C = (const float*)d_in[1];     // context [S,B,D]
    const float* W = (const float*)d_in[2];     // [D, 2D]
    const float* bias = (const float*)d_in[3];  // [D]
    float* out = (float*)d_out;                 // [B,T,D]

    gemm_qk<<<dim3(SS / 128, TT / 128, BB), 256>>>(Q, C);
    softmax_mask<<<dim3(BB * TT), 256>>>();
    gemm_pv<<<dim3(DD / 128, TT / 128, BB), 256>>>(C);
    gemm_out<<<dim3(DD / 128, TT / 128, BB), 256>>>(Q, W, bias, out);
}

// round 3
// speedup vs baseline: 2.4745x; 2.4745x over previous
#include <cuda_runtime.h>
#include <cuda_bf16.h>
#include <math.h>
#include <stdint.h>

#define TT 2048
#define SS 2048
#define BB 16
#define DD 1024
#define KK2 2048

// ---------------- device scratch (static, no runtime alloc) ----------------
__device__ float         g_scores[(size_t)BB * TT * SS];   // 256 MiB
__device__ __nv_bfloat16 g_combH[(size_t)BB * TT * KK2];   // [b][t][0..1023]=mix, [1024..2047]=q
__device__ __nv_bfloat16 g_combL[(size_t)BB * TT * KK2];
__device__ __nv_bfloat16 g_cH[(size_t)BB * SS * DD];       // context hi [b][s][d]
__device__ __nv_bfloat16 g_cL[(size_t)BB * SS * DD];
__device__ __nv_bfloat16 g_cTH[(size_t)BB * DD * SS];      // context^T  [b][d][s]
__device__ __nv_bfloat16 g_cTL[(size_t)BB * DD * SS];
__device__ __nv_bfloat16 g_PH[(size_t)BB * TT * SS];       // probs hi/lo
__device__ __nv_bfloat16 g_PL[(size_t)BB * TT * SS];
__device__ __nv_bfloat16 g_WH[(size_t)DD * KK2];
__device__ __nv_bfloat16 g_WL[(size_t)DD * KK2];

// ---------------- helpers ----------------
__device__ __forceinline__ void split2(float x, __nv_bfloat16& h, __nv_bfloat16& l) {
    h = __float2bfloat16_rn(x);
    l = __float2bfloat16_rn(x - __bfloat162float(h));
}

__device__ __forceinline__ uint32_t smem_u32(const void* p) {
    uint32_t a;
    asm("{ .reg .u64 t; cvta.to.shared.u64 t, %1; cvt.u32.u64 %0, t; }" : "=r"(a) : "l"(p));
    return a;
}

__device__ __forceinline__ void ldsm4(uint32_t* r, uint32_t addr) {
    asm volatile("ldmatrix.sync.aligned.m8n8.x4.shared.b16 {%0,%1,%2,%3}, [%4];"
                 : "=r"(r[0]), "=r"(r[1]), "=r"(r[2]), "=r"(r[3]) : "r"(addr));
}

__device__ __forceinline__ void mma_bf16(float* c, const uint32_t* a, uint32_t b0, uint32_t b1) {
    asm volatile(
        "mma.sync.aligned.m16n8k16.row.col.f32.bf16.bf16.f32 "
        "{%0,%1,%2,%3}, {%4,%5,%6,%7}, {%8,%9}, {%0,%1,%2,%3};"
        : "+f"(c[0]), "+f"(c[1]), "+f"(c[2]), "+f"(c[3])
        : "r"(a[0]), "r"(a[1]), "r"(a[2]), "r"(a[3]), "r"(b0), "r"(b1));
}

// swizzled offset of 16B chunk (row r, 16B-group c16 of a 64B logical row)
// physical: 128B lines hold 2 rows; 8-way XOR swizzle over 16B subs within a line.
__device__ __forceinline__ uint32_t sw_off(int r, int c16) {
    uint32_t line = (uint32_t)(r >> 1);
    uint32_t sub = (uint32_t)(c16 + ((r & 1) << 2));
    return (line << 7) + (((sub ^ (line & 7))) << 4);
}

// ---------------- split-precision bf16 mma.sync GEMM ----------------
// D[m][n] = sum_k (Ah+Al)[m][k]*(Bh+Bl)[n][k]   (drops Al*Bl)
// CTA tile M128 x N128, K-chunk 32, 3 passes folded into extended K loop,
// 4-stage cp.async pipeline. EPI: 0=fp32 store, 1=bf16 hi/lo store, 2=bias+tanh fp32.
#define STAGE_B 16384
#define SMEM_DYN (4 * STAGE_B)

template <int EPI>
__global__ __launch_bounds__(256) void mma_gemm(
    const __nv_bfloat16* __restrict__ Ah, const __nv_bfloat16* __restrict__ Al,
    size_t a_row, size_t a_batch,
    const __nv_bfloat16* __restrict__ Bh, const __nv_bfloat16* __restrict__ Bl,
    size_t b_row, size_t b_batch,
    int KCH,  // K/32
    float* __restrict__ outF, __nv_bfloat16* __restrict__ outH, __nv_bfloat16* __restrict__ outL,
    size_t c_row, size_t c_batch, const float* __restrict__ bias) {
    extern __shared__ char smem[];
    const uint32_t sb = smem_u32(smem);
    const int tid = threadIdx.x;
    const int lane = tid & 31, wid = tid >> 5;
    const int wm = wid & 3, wn = wid >> 2;            // 4 x 2 warp grid (M32, N64 per warp)
    const int n0 = blockIdx.x * 128, m0 = blockIdx.y * 128, bz = blockIdx.z;

    const __nv_bfloat16* A_h = Ah + (size_t)bz * a_batch + (size_t)m0 * a_row;
    const __nv_bfloat16* A_l = Al + (size_t)bz * a_batch + (size_t)m0 * a_row;
    const __nv_bfloat16* B_h = Bh + (size_t)bz * b_batch + (size_t)n0 * b_row;
    const __nv_bfloat16* B_l = Bl + (size_t)bz * b_batch + (size_t)n0 * b_row;

    const int NC = 3 * KCH;

    auto load_stage = [&](int c) {
        const int p = (c >= 2 * KCH) ? 2 : ((c >= KCH) ? 1 : 0);
        const int kk = (c - p * KCH) * 32;
        const __nv_bfloat16* As = (p == 1) ? A_l : A_h;
        const __nv_bfloat16* Bs = (p == 2) ? B_l : B_h;
        const uint32_t st = sb + (uint32_t)(c & 3) * STAGE_B;
#pragma unroll
        for (int i = tid; i < 512; i += 256) {
            const int r = i >> 2, cc = i & 3;
            const char* gp = (const char*)(As + (size_t)r * a_row + kk) + (cc << 4);
            asm volatile("cp.async.cg.shared.global [%0], [%1], 16;"
                         :: "r"(st + sw_off(r, cc)), "l"(gp) : "memory");
        }
#pragma unroll
        for (int i = tid; i < 512; i += 256) {
            const int r = i >> 2, cc = i & 3;
            const char* gp = (const char*)(Bs + (size_t)r * b_row + kk) + (cc << 4);
            asm volatile("cp.async.cg.shared.global [%0], [%1], 16;"
                         :: "r"(st + 8192 + sw_off(r, cc)), "l"(gp) : "memory");
        }
        asm volatile("cp.async.commit_group;" ::: "memory");
    };

    // per-thread ldmatrix offsets (within a stage), k16=0; XOR 32 flips to k16=1
    uint32_t offA[2], offB[4];
    {
        const int gA = lane >> 4;  // 0/1
#pragma unroll
        for (int mi = 0; mi < 2; mi++) {
            const int r = wm * 32 + mi * 16 + (lane & 15);
            offA[mi] = sw_off(r, gA);
        }
        const int gB = (lane >> 3) & 1;
        const int rb = wn * 64 + ((lane >> 4) << 3) + (lane & 7);
#pragma unroll
        for (int nj = 0; nj < 4; nj++) offB[nj] = 8192 + sw_off(rb + nj * 16, gB);
    }

    float acc[2][8][4];
#pragma unroll
    for (int i = 0; i < 2; i++)
#pragma unroll
        for (int j = 0; j < 8; j++)
#pragma unroll
            for (int q = 0; q < 4; q++) acc[i][j][q] = 0.0f;

    load_stage(0);
    load_stage(1);
    load_stage(2);

    for (int c = 0; c < NC; c++) {
        asm volatile("cp.async.wait_group 2;" ::: "memory");
        __syncthreads();
        if (c + 3 < NC) load_stage(c + 3);
        else asm volatile("cp.async.commit_group;" ::: "memory");

        const uint32_t st = sb + (uint32_t)(c & 3) * STAGE_B;
#pragma unroll
        for (int k16 = 0; k16 < 2; k16++) {
            const uint32_t x = (uint32_t)(k16 << 5);
            uint32_t a[2][4], b[4][4];
            ldsm4(a[0], st + (offA[0] ^ x));
            ldsm4(a[1], st + (offA[1] ^ x));
#pragma unroll
            for (int nj = 0; nj < 4; nj++) ldsm4(b[nj], st + (offB[nj] ^ x));
#pragma unroll
            for (int mi = 0; mi < 2; mi++)
#pragma unroll
                for (int nj = 0; nj < 4; nj++) {
                    mma_bf16(acc[mi][2 * nj], a[mi], b[nj][0], b[nj][1]);
                    mma_bf16(acc[mi][2 * nj + 1], a[mi], b[nj][2], b[nj][3]);
                }
        }
    }

    // -------- epilogue --------
    const int trow = lane >> 2, tcol = (lane & 3) * 2;
#pragma unroll
    for (int mi = 0; mi < 2; mi++) {
#pragma unroll
        for (int nj = 0; nj < 8; nj++) {
            const int row = m0 + wm * 32 + mi * 16 + trow;
            const int col = n0 + wn * 64 + nj * 8 + tcol;
            const float* a4 = acc[mi][nj];
            if (EPI == 0) {
                float* p = outF + (size_t)bz * c_batch + (size_t)row * c_row + col;
                *(float2*)p = make_float2(a4[0], a4[1]);
                *(float2*)(p + 8 * c_row) = make_float2(a4[2], a4[3]);
            } else if (EPI == 1) {
                __nv_bfloat16* ph = outH + (size_t)bz * c_batch + (size_t)row * c_row + col;
                __nv_bfloat16* pl = outL + (size_t)bz * c_batch + (size_t)row * c_row + col;
                __nv_bfloat16 h0, l0, h1, l1;
                split2(a4[0], h0, l0);
                split2(a4[1], h1, l1);
                __nv_bfloat162 vh, vl;
                vh.x = h0; vh.y = h1; vl.x = l0; vl.y = l1;
                *(__nv_bfloat162*)ph = vh;
                *(__nv_bfloat162*)pl = vl;
                split2(a4[2], h0, l0);
                split2(a4[3], h1, l1);
                vh.x = h0; vh.y = h1; vl.x = l0; vl.y = l1;
                *(__nv_bfloat162*)(ph + 8 * c_row) = vh;
                *(__nv_bfloat162*)(pl + 8 * c_row) = vl;
            } else {
                const float b0 = bias[col], b1 = bias[col + 1];
                float* p = outF + (size_t)bz * c_batch + (size_t)row * c_row + col;
                *(float2*)p = make_float2(tanhf(a4[0] + b0), tanhf(a4[1] + b1));
                *(float2*)(p + 8 * c_row) = make_float2(tanhf(a4[2] + b0), tanhf(a4[3] + b1));
            }
        }
    }
}

// ---------------- conversion kernels ----------------
__global__ __launch_bounds__(256) void conv_q(const float* __restrict__ Q) {
    size_t i = (size_t)blockIdx.x * 256 + threadIdx.x;  // over T*B*D
    int d = (int)(i & (DD - 1));
    size_t j = i >> 10;
    int b = (int)(j & (BB - 1));
    size_t t = j >> 4;
    __nv_bfloat16 h, l;
    split2(Q[i], h, l);
    size_t o = ((size_t)b * TT + t) * KK2 + DD + d;
    g_combH[o] = h;
    g_combL[o] = l;
}

__global__ __launch_bounds__(256) void conv_c(const float* __restrict__ C) {
    size_t i = (size_t)blockIdx.x * 256 + threadIdx.x;  // over S*B*D
    int d = (int)(i & (DD - 1));
    size_t j = i >> 10;
    int b = (int)(j & (BB - 1));
    size_t s = j >> 4;
    __nv_bfloat16 h, l;
    split2(C[i], h, l);
    size_t o = ((size_t)b * SS + s) * DD + d;
    g_cH[o] = h;
    g_cL[o] = l;
}

__global__ __launch_bounds__(256) void conv_ct(const float* __restrict__ C) {
    __shared__ float tile[32][33];
    const int b = blockIdx.z;
    const int d0 = blockIdx.x * 32, s0 = blockIdx.y * 32;
    const int tx = threadIdx.x, ty = threadIdx.y;  // (32,8)
#pragma unroll
    for (int i = 0; i < 4; i++) {
        int s = s0 + ty + i * 8;
        tile[ty + i * 8][tx] = C[((size_t)s * BB + b) * DD + d0 + tx];
    }
    __syncthreads();
#pragma unroll
    for (int i = 0; i < 4; i++) {
        int d = d0 + ty + i * 8;
        __nv_bfloat16 h, l;
        split2(tile[tx][ty + i * 8], h, l);
        size_t o = ((size_t)b * DD + d) * SS + s0 + tx;
        g_cTH[o] = h;
        g_cTL[o] = l;
    }
}

__global__ __launch_bounds__(256) void conv_w(const float* __restrict__ W) {
    size_t i = (size_t)blockIdx.x * 256 + threadIdx.x;  // over D*2D
    __nv_bfloat16 h, l;
    split2(W[i], h, l);
    g_WH[i] = h;
    g_WL[i] = l;
}

// ---------------- softmax (==0 -> -inf mask), fp32 scores -> bf16 hi/lo probs ----------------
__global__ __launch_bounds__(256) void softmax_mask() {
    const size_t rowi = blockIdx.x;
    const float* p = g_scores + rowi * SS;
    __nv_bfloat16* ph = g_PH + rowi * SS;
    __nv_bfloat16* pl = g_PL + rowi * SS;
    const int tid = threadIdx.x;
    __shared__ float red[256];
    float v[8];
    float m = -INFINITY;
#pragma unroll
    for (int i = 0; i < 8; i++) {
        v[i] = p[tid + i * 256];
        float x = (v[i] == 0.0f) ? -INFINITY : v[i];
        m = fmaxf(m, x);
    }
    red[tid] = m;
    __syncthreads();
#pragma unroll
    for (int s = 128; s > 0; s >>= 1) {
        if (tid < s) red[tid] = fmaxf(red[tid], red[tid + s]);
        __syncthreads();
    }
    m = red[0];
    __syncthreads();
    float e[8];
    float sum = 0.0f;
#pragma unroll
    for (int i = 0; i < 8; i++) {
        e[i] = (v[i] == 0.0f) ? 0.0f : __expf(v[i] - m);
        sum += e[i];
    }
    red[tid] = sum;
    __syncthreads();
#pragma unroll
    for (int s = 128; s > 0; s >>= 1) {
        if (tid < s) red[tid] += red[tid + s];
        __syncthreads();
    }
    const float inv = 1.0f / red[0];
#pragma unroll
    for (int i = 0; i < 8; i++) {
        __nv_bfloat16 h, l;
        split2(e[i] * inv, h, l);
        ph[tid + i * 256] = h;
        pl[tid + i * 256] = l;
    }
}

// ---------------- launch ----------------
extern "C" void kernel_launch(void* const* d_in, const int* in_sizes, int n_in,
                              void* d_out, int out_size) {
    (void)in_sizes; (void)n_in; (void)out_size;
    const float* Q = (const float*)d_in[0];
    const float* C = (const float*)d_in[1];
    const float* W = (const float*)d_in[2];
    const float* bias = (const float*)d_in[3];
    float* out = (float*)d_out;

    void *pScores, *pCombH, *pCombL, *pCH, *pCL, *pCTH, *pCTL, *pPH, *pPL, *pWH, *pWL;
    cudaGetSymbolAddress(&pScores, g_scores);
    cudaGetSymbolAddress(&pCombH, g_combH);
    cudaGetSymbolAddress(&pCombL, g_combL);
    cudaGetSymbolAddress(&pCH, g_cH);
    cudaGetSymbolAddress(&pCL, g_cL);
    cudaGetSymbolAddress(&pCTH, g_cTH);
    cudaGetSymbolAddress(&pCTL, g_cTL);
    cudaGetSymbolAddress(&pPH, g_PH);
    cudaGetSymbolAddress(&pPL, g_PL);
    cudaGetSymbolAddress(&pWH, g_WH);
    cudaGetSymbolAddress(&pWL, g_WL);

    cudaFuncSetAttribute(mma_gemm<0>, cudaFuncAttributeMaxDynamicSharedMemorySize, SMEM_DYN);
    cudaFuncSetAttribute(mma_gemm<1>, cudaFuncAttributeMaxDynamicSharedMemorySize, SMEM_DYN);
    cudaFuncSetAttribute(mma_gemm<2>, cudaFuncAttributeMaxDynamicSharedMemorySize, SMEM_DYN);

    // conversions
    conv_q<<<(unsigned)((size_t)TT * BB * DD / 256), 256>>>(Q);
    conv_c<<<(unsigned)((size_t)SS * BB * DD / 256), 256>>>(C);
    conv_ct<<<dim3(DD / 32, SS / 32, BB), dim3(32, 8)>>>(C);
    conv_w<<<(unsigned)((size_t)DD * KK2 / 256), 256>>>(W);

    // GEMM1: scores[b][t][s] = q . c
    mma_gemm<0><<<dim3(SS / 128, TT / 128, BB), 256, SMEM_DYN>>>(
        (const __nv_bfloat16*)pCombH + DD, (const __nv_bfloat16*)pCombL + DD,
        (size_t)KK2, (size_t)TT * KK2,
        (const __nv_bfloat16*)pCH, (const __nv_bfloat16*)pCL,
        (size_t)DD, (size_t)SS * DD,
        DD / 32,
        (float*)pScores, nullptr, nullptr, (size_t)SS, (size_t)TT * SS, nullptr);

    softmax_mask<<<BB * TT, 256>>>();

    // GEMM2: mix[b][t][d] = P . cT  -> bf16 hi/lo into comb cols [0,1024)
    mma_gemm<1><<<dim3(DD / 128, TT / 128, BB), 256, SMEM_DYN>>>(
        (const __nv_bfloat16*)pPH, (const __nv_bfloat16*)pPL,
        (size_t)SS, (size_t)TT * SS,
        (const __nv_bfloat16*)pCTH, (const __nv_bfloat16*)pCTL,
        (size_t)SS, (size_t)DD * SS,
        SS / 32,
        nullptr, (__nv_bfloat16*)pCombH, (__nv_bfloat16*)pCombL,
        (size_t)KK2, (size_t)TT * KK2, nullptr);

    // GEMM3: out[b][t][d] = tanh(comb . W^T + bias)
    mma_gemm<2><<<dim3(DD / 128, TT / 128, BB), 256, SMEM_DYN>>>(
        (const __nv_bfloat16*)pCombH, (const __nv_bfloat16*)pCombL,
        (size_t)KK2, (size_t)TT * KK2,
        (const __nv_bfloat16*)pWH, (const __nv_bfloat16*)pWL,
        (size_t)KK2, (size_t)0,
        KK2 / 32,
        out, nullptr, nullptr, (size_t)DD, (size_t)TT * DD, bias);
}

// round 4
// speedup vs baseline: 3.0950x; 1.2507x over previous
#include <cuda_runtime.h>
#include <cuda_fp16.h>
#include <math.h>
#include <stdint.h>

#define TT 2048
#define SS 2048
#define BB 16
#define DD 1024
#define KK2 2048

// ---------------- device scratch (static) ----------------
__device__ float  g_scores[(size_t)BB * TT * SS];   // 256 MiB
__device__ __half g_combH[(size_t)BB * TT * KK2];   // [b][t][0..1023]=mix, [1024..2047]=q
__device__ __half g_combL[(size_t)BB * TT * KK2];
__device__ __half g_cH[(size_t)BB * SS * DD];       // context hi [b][s][d]
__device__ __half g_cL[(size_t)BB * SS * DD];
__device__ __half g_cTH[(size_t)BB * DD * SS];      // context^T [b][d][s]
__device__ __half g_cTL[(size_t)BB * DD * SS];
__device__ __half g_PH[(size_t)BB * TT * SS];       // probs hi/lo
__device__ __half g_PL[(size_t)BB * TT * SS];
__device__ __half g_WH[(size_t)DD * KK2];
__device__ __half g_WL[(size_t)DD * KK2];

// ---------------- helpers ----------------
__device__ __forceinline__ void split2(float x, __half& h, __half& l) {
    h = __float2half_rn(x);
    l = __float2half_rn(x - __half2float(h));
}

__device__ __forceinline__ uint32_t smem_u32(const void* p) {
    uint32_t a;
    asm("{ .reg .u64 t; cvta.to.shared.u64 t, %1; cvt.u32.u64 %0, t; }" : "=r"(a) : "l"(p));
    return a;
}

__device__ __forceinline__ void ldsm4(uint32_t* r, uint32_t addr) {
    asm volatile("ldmatrix.sync.aligned.m8n8.x4.shared.b16 {%0,%1,%2,%3}, [%4];"
                 : "=r"(r[0]), "=r"(r[1]), "=r"(r[2]), "=r"(r[3]) : "r"(addr));
}

__device__ __forceinline__ void mma_f16(float* c, const uint32_t* a, uint32_t b0, uint32_t b1) {
    asm volatile(
        "mma.sync.aligned.m16n8k16.row.col.f32.f16.f16.f32 "
        "{%0,%1,%2,%3}, {%4,%5,%6,%7}, {%8,%9}, {%0,%1,%2,%3};"
        : "+f"(c[0]), "+f"(c[1]), "+f"(c[2]), "+f"(c[3])
        : "r"(a[0]), "r"(a[1]), "r"(a[2]), "r"(a[3]), "r"(b0), "r"(b1));
}

// swizzled byte offset of 16B chunk (row r of 128B, chunk c16 in 0..7)
__device__ __forceinline__ uint32_t sw_off(int r, int c16) {
    return ((uint32_t)r << 7) + (((uint32_t)(c16 ^ (r & 7))) << 4);
}

// ---------------- split-precision fp16 mma.sync GEMM ----------------
// NP=3: Ah*Bh + Al*Bh + Ah*Bl ; NP=2: Ah*Bh + Al*Bh
// CTA tile M128 x N128, K-chunk 64, 3-stage cp.async pipeline, 8 warps (warp 32x64).
// EPI: 0=fp32 store, 1=fp16 hi/lo store, 2=bias+tanh fp32.
#define STAGE_B 32768
#define NSTG 3
#define SMEM_DYN (NSTG * STAGE_B)

template <int EPI>
__global__ __launch_bounds__(256) void mma_gemm(
    const __half* __restrict__ Ah, const __half* __restrict__ Al,
    size_t a_row, size_t a_batch,
    const __half* __restrict__ Bh, const __half* __restrict__ Bl,
    size_t b_row, size_t b_batch,
    int KCH, int NP,  // K/64, number of passes
    float* __restrict__ outF, __half* __restrict__ outH, __half* __restrict__ outL,
    size_t c_row, size_t c_batch, const float* __restrict__ bias) {
    extern __shared__ char smem[];
    const uint32_t sb = smem_u32(smem);
    const int tid = threadIdx.x;
    const int lane = tid & 31, wid = tid >> 5;
    const int wm = wid & 3, wn = wid >> 2;  // 4x2 warp grid: warp tile M32 x N64
    const int n0 = blockIdx.x * 128, m0 = blockIdx.y * 128, bz = blockIdx.z;

    const __half* A_h = Ah + (size_t)bz * a_batch + (size_t)m0 * a_row;
    const __half* A_l = Al + (size_t)bz * a_batch + (size_t)m0 * a_row;
    const __half* B_h = Bh + (size_t)bz * b_batch + (size_t)n0 * b_row;
    const __half* B_l = Bl + (size_t)bz * b_batch + (size_t)n0 * b_row;

    const int NC = NP * KCH;

    auto load_stage = [&](int c) {
        const int p = c / KCH;  // 0:hh 1:lh 2:hl
        const int kk = (c - p * KCH) * 64;
        const __half* As = (p == 1) ? A_l : A_h;
        const __half* Bs = (p == 2) ? B_l : B_h;
        const uint32_t st = sb + (uint32_t)(c % NSTG) * STAGE_B;
#pragma unroll
        for (int i = tid; i < 1024; i += 256) {
            const int r = i >> 3, cc = i & 7;
            const char* gp = (const char*)(As + (size_t)r * a_row + kk) + (cc << 4);
            asm volatile("cp.async.cg.shared.global [%0], [%1], 16;"
                         :: "r"(st + sw_off(r, cc)), "l"(gp) : "memory");
        }
#pragma unroll
        for (int i = tid; i < 1024; i += 256) {
            const int r = i >> 3, cc = i & 7;
            const char* gp = (const char*)(Bs + (size_t)r * b_row + kk) + (cc << 4);
            asm volatile("cp.async.cg.shared.global [%0], [%1], 16;"
                         :: "r"(st + 16384 + sw_off(r, cc)), "l"(gp) : "memory");
        }
        asm volatile("cp.async.commit_group;" ::: "memory");
    };

    // per-thread ldmatrix base offsets (k16 step j applied via XOR j<<5)
    uint32_t offA[2], offB[4];
    {
        const int gA = lane >> 4;
#pragma unroll
        for (int mi = 0; mi < 2; mi++)
            offA[mi] = sw_off(wm * 32 + mi * 16 + (lane & 15), gA);
        const int gB = (lane >> 3) & 1;
        const int rb = wn * 64 + ((lane >> 4) << 3) + (lane & 7);
#pragma unroll
        for (int nj = 0; nj < 4; nj++) offB[nj] = 16384 + sw_off(rb + nj * 16, gB);
    }

    float acc[2][8][4];
#pragma unroll
    for (int i = 0; i < 2; i++)
#pragma unroll
        for (int j = 0; j < 8; j++)
#pragma unroll
            for (int q = 0; q < 4; q++) acc[i][j][q] = 0.0f;

    load_stage(0);
    load_stage(1);

    for (int c = 0; c < NC; c++) {
        asm volatile("cp.async.wait_group 1;" ::: "memory");
        __syncthreads();
        if (c + 2 < NC) load_stage(c + 2);
        else asm volatile("cp.async.commit_group;" ::: "memory");

        const uint32_t st = sb + (uint32_t)(c % NSTG) * STAGE_B;
#pragma unroll
        for (int k16 = 0; k16 < 4; k16++) {
            const uint32_t x = (uint32_t)(k16 << 5);
            uint32_t a[2][4], b[4][4];
            ldsm4(a[0], st + (offA[0] ^ x));
            ldsm4(a[1], st + (offA[1] ^ x));
#pragma unroll
            for (int nj = 0; nj < 4; nj++) ldsm4(b[nj], st + (offB[nj] ^ x));
#pragma unroll
            for (int mi = 0; mi < 2; mi++)
#pragma unroll
                for (int nj = 0; nj < 4; nj++) {
                    mma_f16(acc[mi][2 * nj], a[mi], b[nj][0], b[nj][1]);
                    mma_f16(acc[mi][2 * nj + 1], a[mi], b[nj][2], b[nj][3]);
                }
        }
    }

    // -------- epilogue --------
    const int trow = lane >> 2, tcol = (lane & 3) * 2;
#pragma unroll
    for (int mi = 0; mi < 2; mi++) {
#pragma unroll
        for (int nj = 0; nj < 8; nj++) {
            const int row = m0 + wm * 32 + mi * 16 + trow;
            const int col = n0 + wn * 64 + nj * 8 + tcol;
            const float* a4 = acc[mi][nj];
            if (EPI == 0) {
                float* p = outF + (size_t)bz * c_batch + (size_t)row * c_row + col;
                *(float2*)p = make_float2(a4[0], a4[1]);
                *(float2*)(p + 8 * c_row) = make_float2(a4[2], a4[3]);
            } else if (EPI == 1) {
                __half* ph = outH + (size_t)bz * c_batch + (size_t)row * c_row + col;
                __half* pl = outL + (size_t)bz * c_batch + (size_t)row * c_row + col;
                __half h0, l0, h1, l1;
                split2(a4[0], h0, l0);
                split2(a4[1], h1, l1);
                __half2 vh, vl;
                vh.x = h0; vh.y = h1; vl.x = l0; vl.y = l1;
                *(__half2*)ph = vh;
                *(__half2*)pl = vl;
                split2(a4[2], h0, l0);
                split2(a4[3], h1, l1);
                vh.x = h0; vh.y = h1; vl.x = l0; vl.y = l1;
                *(__half2*)(ph + 8 * c_row) = vh;
                *(__half2*)(pl + 8 * c_row) = vl;
            } else {
                const float b0 = bias[col], b1 = bias[col + 1];
                float* p = outF + (size_t)bz * c_batch + (size_t)row * c_row + col;
                *(float2*)p = make_float2(tanhf(a4[0] + b0), tanhf(a4[1] + b1));
                *(float2*)(p + 8 * c_row) = make_float2(tanhf(a4[2] + b0), tanhf(a4[3] + b1));
            }
        }
    }
}

// ---------------- conversion kernels ----------------
__global__ __launch_bounds__(256) void conv_q(const float* __restrict__ Q) {
    size_t i = (size_t)blockIdx.x * 256 + threadIdx.x;  // over T*B*D
    int d = (int)(i & (DD - 1));
    size_t j = i >> 10;
    int b = (int)(j & (BB - 1));
    size_t t = j >> 4;
    __half h, l;
    split2(Q[i], h, l);
    size_t o = ((size_t)b * TT + t) * KK2 + DD + d;
    g_combH[o] = h;
    g_combL[o] = l;
}

// merged: straight split layout [b][s][d] AND transposed [b][d][s]; reads C once
__global__ __launch_bounds__(256) void conv_c_ct(const float* __restrict__ C) {
    __shared__ float tile[32][33];
    const int b = blockIdx.z;
    const int d0 = blockIdx.x * 32, s0 = blockIdx.y * 32;
    const int tx = threadIdx.x, ty = threadIdx.y;  // (32,8)
#pragma unroll
    for (int i = 0; i < 4; i++) {
        int s = s0 + ty + i * 8;
        float v = C[((size_t)s * BB + b) * DD + d0 + tx];
        tile[ty + i * 8][tx] = v;
        __half h, l;
        split2(v, h, l);
        size_t o = ((size_t)b * SS + s) * DD + d0 + tx;
        g_cH[o] = h;
        g_cL[o] = l;
    }
    __syncthreads();
#pragma unroll
    for (int i = 0; i < 4; i++) {
        int d = d0 + ty + i * 8;
        __half h, l;
        split2(tile[tx][ty + i * 8], h, l);
        size_t o = ((size_t)b * DD + d) * SS + s0 + tx;
        g_cTH[o] = h;
        g_cTL[o] = l;
    }
}

__global__ __launch_bounds__(256) void conv_w(const float* __restrict__ W) {
    size_t i = (size_t)blockIdx.x * 256 + threadIdx.x;  // over D*2D
    __half h, l;
    split2(W[i], h, l);
    g_WH[i] = h;
    g_WL[i] = l;
}

// ---------------- softmax (==0 -> -inf mask), fp32 scores -> fp16 hi/lo probs ----------------
__global__ __launch_bounds__(256) void softmax_mask() {
    const size_t rowi = blockIdx.x;
    const float* p = g_scores + rowi * SS;
    __half* ph = g_PH + rowi * SS;
    __half* pl = g_PL + rowi * SS;
    const int tid = threadIdx.x;
    __shared__ float red[256];
    float v[8];
    float m = -INFINITY;
#pragma unroll
    for (int i = 0; i < 8; i++) {
        v[i] = p[tid + i * 256];
        float x = (v[i] == 0.0f) ? -INFINITY : v[i];
        m = fmaxf(m, x);
    }
    red[tid] = m;
    __syncthreads();
#pragma unroll
    for (int s = 128; s > 0; s >>= 1) {
        if (tid < s) red[tid] = fmaxf(red[tid], red[tid + s]);
        __syncthreads();
    }
    m = red[0];
    __syncthreads();
    float e[8];
    float sum = 0.0f;
#pragma unroll
    for (int i = 0; i < 8; i++) {
        e[i] = (v[i] == 0.0f) ? 0.0f : __expf(v[i] - m);
        sum += e[i];
    }
    red[tid] = sum;
    __syncthreads();
#pragma unroll
    for (int s = 128; s > 0; s >>= 1) {
        if (tid < s) red[tid] += red[tid + s];
        __syncthreads();
    }
    const float inv = 1.0f / red[0];
#pragma unroll
    for (int i = 0; i < 8; i++) {
        __half h, l;
        split2(e[i] * inv, h, l);
        ph[tid + i * 256] = h;
        pl[tid + i * 256] = l;
    }
}

// ---------------- launch ----------------
extern "C" void kernel_launch(void* const* d_in, const int* in_sizes, int n_in,
                              void* d_out, int out_size) {
    (void)in_sizes; (void)n_in; (void)out_size;
    const float* Q = (const float*)d_in[0];
    const float* C = (const float*)d_in[1];
    const float* W = (const float*)d_in[2];
    const float* bias = (const float*)d_in[3];
    float* out = (float*)d_out;

    void *pScores, *pCombH, *pCombL, *pCH, *pCL, *pCTH, *pCTL, *pPH, *pPL, *pWH, *pWL;
    cudaGetSymbolAddress(&pScores, g_scores);
    cudaGetSymbolAddress(&pCombH, g_combH);
    cudaGetSymbolAddress(&pCombL, g_combL);
    cudaGetSymbolAddress(&pCH, g_cH);
    cudaGetSymbolAddress(&pCL, g_cL);
    cudaGetSymbolAddress(&pCTH, g_cTH);
    cudaGetSymbolAddress(&pCTL, g_cTL);
    cudaGetSymbolAddress(&pPH, g_PH);
    cudaGetSymbolAddress(&pPL, g_PL);
    cudaGetSymbolAddress(&pWH, g_WH);
    cudaGetSymbolAddress(&pWL, g_WL);

    cudaFuncSetAttribute(mma_gemm<0>, cudaFuncAttributeMaxDynamicSharedMemorySize, SMEM_DYN);
    cudaFuncSetAttribute(mma_gemm<1>, cudaFuncAttributeMaxDynamicSharedMemorySize, SMEM_DYN);
    cudaFuncSetAttribute(mma_gemm<2>, cudaFuncAttributeMaxDynamicSharedMemorySize, SMEM_DYN);

    // conversions
    conv_q<<<(unsigned)((size_t)TT * BB * DD / 256), 256>>>(Q);
    conv_c_ct<<<dim3(DD / 32, SS / 32, BB), dim3(32, 8)>>>(C);
    conv_w<<<(unsigned)((size_t)DD * KK2 / 256), 256>>>(W);

    // GEMM1: scores = q . c   (3 passes: hh + lh + hl)
    mma_gemm<0><<<dim3(SS / 128, TT / 128, BB), 256, SMEM_DYN>>>(
        (const __half*)pCombH + DD, (const __half*)pCombL + DD,
        (size_t)KK2, (size_t)TT * KK2,
        (const __half*)pCH, (const __half*)pCL,
        (size_t)DD, (size_t)SS * DD,
        DD / 64, 3,
        (float*)pScores, nullptr, nullptr, (size_t)SS, (size_t)TT * SS, nullptr);

    softmax_mask<<<BB * TT, 256>>>();

    // GEMM2: mix = P . cT   (2 passes: hh + lh) -> fp16 hi/lo into comb cols [0,1024)
    mma_gemm<1><<<dim3(DD / 128, TT / 128, BB), 256, SMEM_DYN>>>(
        (const __half*)pPH, (const __half*)pPL,
        (size_t)SS, (size_t)TT * SS,
        (const __half*)pCTH, (const __half*)pCTL,
        (size_t)SS, (size_t)DD * SS,
        SS / 64, 2,
        nullptr, (__half*)pCombH, (__half*)pCombL,
        (size_t)KK2, (size_t)TT * KK2, nullptr);

    // GEMM3: out = tanh(comb . W^T + bias)   (2 passes: hh + lh)
    mma_gemm<2><<<dim3(DD / 128, TT / 128, BB), 256, SMEM_DYN>>>(
        (const __half*)pCombH, (const __half*)pCombL,
        (size_t)KK2, (size_t)TT * KK2,
        (const __half*)pWH, (const __half*)pWL,
        (size_t)KK2, (size_t)0,
        KK2 / 64, 2,
        out, nullptr, nullptr, (size_t)DD, (size_t)TT * DD, bias);
}

// round 5
// speedup vs baseline: 3.2483x; 1.0495x over previous
#include <cuda_runtime.h>
#include <cuda_fp16.h>
#include <math.h>
#include <stdint.h>

#define TT 2048
#define SS 2048
#define BB 16
#define DD 1024
#define KK2 2048

// ---------------- device scratch (static) ----------------
__device__ float  g_scores[(size_t)BB * TT * SS];   // 256 MiB
__device__ __half g_combH[(size_t)BB * TT * KK2];   // [b][t][0..1023]=mix, [1024..2047]=q
__device__ __half g_combL[(size_t)BB * TT * KK2];
__device__ __half g_cH[(size_t)BB * SS * DD];       // context hi [b][s][d]
__device__ __half g_cL[(size_t)BB * SS * DD];
__device__ __half g_cTH[(size_t)BB * DD * SS];      // context^T [b][d][s]
__device__ __half g_cTL[(size_t)BB * DD * SS];
__device__ __half g_PH[(size_t)BB * TT * SS];       // probs hi/lo
__device__ __half g_PL[(size_t)BB * TT * SS];
__device__ __half g_WH[(size_t)DD * KK2];
__device__ __half g_WL[(size_t)DD * KK2];

// ---------------- helpers ----------------
__device__ __forceinline__ void split2(float x, __half& h, __half& l) {
    h = __float2half_rn(x);
    l = __float2half_rn(x - __half2float(h));
}

__device__ __forceinline__ uint32_t smem_u32(const void* p) {
    uint32_t a;
    asm("{ .reg .u64 t; cvta.to.shared.u64 t, %1; cvt.u32.u64 %0, t; }" : "=r"(a) : "l"(p));
    return a;
}

__device__ __forceinline__ void ldsm4(uint32_t* r, uint32_t addr) {
    asm volatile("ldmatrix.sync.aligned.m8n8.x4.shared.b16 {%0,%1,%2,%3}, [%4];"
                 : "=r"(r[0]), "=r"(r[1]), "=r"(r[2]), "=r"(r[3]) : "r"(addr));
}

__device__ __forceinline__ void mma_f16(float* c, const uint32_t* a, uint32_t b0, uint32_t b1) {
    asm volatile(
        "mma.sync.aligned.m16n8k16.row.col.f32.f16.f16.f32 "
        "{%0,%1,%2,%3}, {%4,%5,%6,%7}, {%8,%9}, {%0,%1,%2,%3};"
        : "+f"(c[0]), "+f"(c[1]), "+f"(c[2]), "+f"(c[3])
        : "r"(a[0]), "r"(a[1]), "r"(a[2]), "r"(a[3]), "r"(b0), "r"(b1));
}

// 64B logical rows (K=32 fp16), 2 rows per 128B line, 8-sub XOR swizzle (validated R3)
__device__ __forceinline__ uint32_t sw_off(int r, int c16) {
    uint32_t line = (uint32_t)(r >> 1);
    uint32_t sub = (uint32_t)(c16 + ((r & 1) << 2));
    return (line << 7) + ((sub ^ (line & 7)) << 4);
}

// ---------------- fused split-precision fp16 mma.sync GEMM ----------------
// One K sweep; per 32-K chunk loads Ah, Al, Bh(, Bl) and accumulates:
//   NP=3: Ah*Bh + Al*Bh + Ah*Bl      NP=2: Ah*Bh + Al*Bh
// CTA tile M128 x N128, 8 warps (warp 32x64), cp.async ring.
// EPI: 0=fp32 store, 1=fp16 hi/lo store, 2=bias+tanh fp32.
#define TILE_B 8192
#define SMEM_DYN 98304

template <int EPI, int NP>
__global__ __launch_bounds__(256) void mma_gemm(
    const __half* __restrict__ Ah, const __half* __restrict__ Al,
    size_t a_row, size_t a_batch,
    const __half* __restrict__ Bh, const __half* __restrict__ Bl,
    size_t b_row, size_t b_batch,
    int KCH,  // K/32
    float* __restrict__ outF, __half* __restrict__ outH, __half* __restrict__ outL,
    size_t c_row, size_t c_batch, const float* __restrict__ bias) {
    constexpr int NT = (NP == 3) ? 4 : 3;       // tiles per stage
    constexpr int NSTG = (NP == 3) ? 3 : 4;     // ring depth (both = 96KB)
    constexpr uint32_t STAGE_B = NT * TILE_B;
    constexpr uint32_t AH_OFF = 0, AL_OFF = TILE_B, BH_OFF = 2 * TILE_B, BL_OFF = 3 * TILE_B;

    extern __shared__ char smem[];
    const uint32_t sb = smem_u32(smem);
    const int tid = threadIdx.x;
    const int lane = tid & 31, wid = tid >> 5;
    const int wm = wid & 3, wn = wid >> 2;  // 4x2 warp grid
    const int n0 = blockIdx.x * 128, m0 = blockIdx.y * 128, bz = blockIdx.z;

    const __half* A_h = Ah + (size_t)bz * a_batch + (size_t)m0 * a_row;
    const __half* A_l = Al + (size_t)bz * a_batch + (size_t)m0 * a_row;
    const __half* B_h = Bh + (size_t)bz * b_batch + (size_t)n0 * b_row;
    const __half* B_l = (NP == 3) ? (Bl + (size_t)bz * b_batch + (size_t)n0 * b_row) : nullptr;

    auto load_tile = [&](uint32_t dst, const __half* g, size_t rstride, int kk) {
#pragma unroll
        for (int i = tid; i < 512; i += 256) {
            const int r = i >> 2, cc = i & 3;
            const char* gp = (const char*)(g + (size_t)r * rstride + kk) + (cc << 4);
            asm volatile("cp.async.cg.shared.global [%0], [%1], 16;"
                         :: "r"(dst + sw_off(r, cc)), "l"(gp) : "memory");
        }
    };
    auto load_stage = [&](int c) {
        const int kk = c * 32;
        const uint32_t st = sb + (uint32_t)(c % NSTG) * STAGE_B;
        load_tile(st + AH_OFF, A_h, a_row, kk);
        load_tile(st + AL_OFF, A_l, a_row, kk);
        load_tile(st + BH_OFF, B_h, b_row, kk);
        if (NP == 3) load_tile(st + BL_OFF, B_l, b_row, kk);
        asm volatile("cp.async.commit_group;" ::: "memory");
    };

    // per-thread ldmatrix offsets within an 8KB tile (k16 step via XOR 0x20)
    uint32_t offA[2], offB[4];
    {
        const int gA = lane >> 4;
#pragma unroll
        for (int mi = 0; mi < 2; mi++)
            offA[mi] = sw_off(wm * 32 + mi * 16 + (lane & 15), gA);
        const int gB = (lane >> 3) & 1;
        const int rb = wn * 64 + ((lane >> 4) << 3) + (lane & 7);
#pragma unroll
        for (int nj = 0; nj < 4; nj++) offB[nj] = sw_off(rb + nj * 16, gB);
    }

    float acc[2][8][4];
#pragma unroll
    for (int i = 0; i < 2; i++)
#pragma unroll
        for (int j = 0; j < 8; j++)
#pragma unroll
            for (int q = 0; q < 4; q++) acc[i][j][q] = 0.0f;

#pragma unroll
    for (int s = 0; s < NSTG - 1; s++) load_stage(s);

    for (int c = 0; c < KCH; c++) {
        asm volatile("cp.async.wait_group %0;" :: "n"(NSTG - 2) : "memory");
        __syncthreads();
        if (c + NSTG - 1 < KCH) load_stage(c + NSTG - 1);
        else asm volatile("cp.async.commit_group;" ::: "memory");

        const uint32_t st = sb + (uint32_t)(c % NSTG) * STAGE_B;
#pragma unroll
        for (int k16 = 0; k16 < 2; k16++) {
            const uint32_t x = (uint32_t)(k16 << 5);
            uint32_t ah[2][4], al[2][4];
            ldsm4(ah[0], st + AH_OFF + (offA[0] ^ x));
            ldsm4(ah[1], st + AH_OFF + (offA[1] ^ x));
            ldsm4(al[0], st + AL_OFF + (offA[0] ^ x));
            ldsm4(al[1], st + AL_OFF + (offA[1] ^ x));
#pragma unroll
            for (int nj = 0; nj < 4; nj++) {
                uint32_t bh[4];
                ldsm4(bh, st + BH_OFF + (offB[nj] ^ x));
                mma_f16(acc[0][2 * nj], ah[0], bh[0], bh[1]);
                mma_f16(acc[0][2 * nj + 1], ah[0], bh[2], bh[3]);
                mma_f16(acc[1][2 * nj], ah[1], bh[0], bh[1]);
                mma_f16(acc[1][2 * nj + 1], ah[1], bh[2], bh[3]);
                mma_f16(acc[0][2 * nj], al[0], bh[0], bh[1]);
                mma_f16(acc[0][2 * nj + 1], al[0], bh[2], bh[3]);
                mma_f16(acc[1][2 * nj], al[1], bh[0], bh[1]);
                mma_f16(acc[1][2 * nj + 1], al[1], bh[2], bh[3]);
                if (NP == 3) {
                    uint32_t bl[4];
                    ldsm4(bl, st + BL_OFF + (offB[nj] ^ x));
                    mma_f16(acc[0][2 * nj], ah[0], bl[0], bl[1]);
                    mma_f16(acc[0][2 * nj + 1], ah[0], bl[2], bl[3]);
                    mma_f16(acc[1][2 * nj], ah[1], bl[0], bl[1]);
                    mma_f16(acc[1][2 * nj + 1], ah[1], bl[2], bl[3]);
                }
            }
        }
    }

    // -------- epilogue --------
    const int trow = lane >> 2, tcol = (lane & 3) * 2;
#pragma unroll
    for (int mi = 0; mi < 2; mi++) {
#pragma unroll
        for (int nj = 0; nj < 8; nj++) {
            const int row = m0 + wm * 32 + mi * 16 + trow;
            const int col = n0 + wn * 64 + nj * 8 + tcol;
            const float* a4 = acc[mi][nj];
            if (EPI == 0) {
                float* p = outF + (size_t)bz * c_batch + (size_t)row * c_row + col;
                *(float2*)p = make_float2(a4[0], a4[1]);
                *(float2*)(p + 8 * c_row) = make_float2(a4[2], a4[3]);
            } else if (EPI == 1) {
                __half* ph = outH + (size_t)bz * c_batch + (size_t)row * c_row + col;
                __half* pl = outL + (size_t)bz * c_batch + (size_t)row * c_row + col;
                __half h0, l0, h1, l1;
                split2(a4[0], h0, l0);
                split2(a4[1], h1, l1);
                __half2 vh, vl;
                vh.x = h0; vh.y = h1; vl.x = l0; vl.y = l1;
                *(__half2*)ph = vh;
                *(__half2*)pl = vl;
                split2(a4[2], h0, l0);
                split2(a4[3], h1, l1);
                vh.x = h0; vh.y = h1; vl.x = l0; vl.y = l1;
                *(__half2*)(ph + 8 * c_row) = vh;
                *(__half2*)(pl + 8 * c_row) = vl;
            } else {
                const float b0 = bias[col], b1 = bias[col + 1];
                float* p = outF + (size_t)bz * c_batch + (size_t)row * c_row + col;
                *(float2*)p = make_float2(tanhf(a4[0] + b0), tanhf(a4[1] + b1));
                *(float2*)(p + 8 * c_row) = make_float2(tanhf(a4[2] + b0), tanhf(a4[3] + b1));
            }
        }
    }
}

// ---------------- conversion kernels ----------------
__global__ __launch_bounds__(256) void conv_q(const float* __restrict__ Q) {
    size_t i = (size_t)blockIdx.x * 256 + threadIdx.x;  // over T*B*D
    int d = (int)(i & (DD - 1));
    size_t j = i >> 10;
    int b = (int)(j & (BB - 1));
    size_t t = j >> 4;
    __half h, l;
    split2(Q[i], h, l);
    size_t o = ((size_t)b * TT + t) * KK2 + DD + d;
    g_combH[o] = h;
    g_combL[o] = l;
}

__global__ __launch_bounds__(256) void conv_c_ct(const float* __restrict__ C) {
    __shared__ float tile[32][33];
    const int b = blockIdx.z;
    const int d0 = blockIdx.x * 32, s0 = blockIdx.y * 32;
    const int tx = threadIdx.x, ty = threadIdx.y;  // (32,8)
#pragma unroll
    for (int i = 0; i < 4; i++) {
        int s = s0 + ty + i * 8;
        float v = C[((size_t)s * BB + b) * DD + d0 + tx];
        tile[ty + i * 8][tx] = v;
        __half h, l;
        split2(v, h, l);
        size_t o = ((size_t)b * SS + s) * DD + d0 + tx;
        g_cH[o] = h;
        g_cL[o] = l;
    }
    __syncthreads();
#pragma unroll
    for (int i = 0; i < 4; i++) {
        int d = d0 + ty + i * 8;
        __half h, l;
        split2(tile[tx][ty + i * 8], h, l);
        size_t o = ((size_t)b * DD + d) * SS + s0 + tx;
        g_cTH[o] = h;
        g_cTL[o] = l;
    }
}

__global__ __launch_bounds__(256) void conv_w(const float* __restrict__ W) {
    size_t i = (size_t)blockIdx.x * 256 + threadIdx.x;  // over D*2D
    __half h, l;
    split2(W[i], h, l);
    g_WH[i] = h;
    g_WL[i] = l;
}

// ---------------- softmax (==0 -> -inf mask), fp32 scores -> fp16 hi/lo probs ----------------
__global__ __launch_bounds__(256) void softmax_mask() {
    const size_t rowi = blockIdx.x;
    const float* p = g_scores + rowi * SS;
    __half* ph = g_PH + rowi * SS;
    __half* pl = g_PL + rowi * SS;
    const int tid = threadIdx.x;
    __shared__ float red[256];
    float v[8];
    float m = -INFINITY;
#pragma unroll
    for (int i = 0; i < 8; i++) {
        v[i] = p[tid + i * 256];
        float x = (v[i] == 0.0f) ? -INFINITY : v[i];
        m = fmaxf(m, x);
    }
    red[tid] = m;
    __syncthreads();
#pragma unroll
    for (int s = 128; s > 0; s >>= 1) {
        if (tid < s) red[tid] = fmaxf(red[tid], red[tid + s]);
        __syncthreads();
    }
    m = red[0];
    __syncthreads();
    float e[8];
    float sum = 0.0f;
#pragma unroll
    for (int i = 0; i < 8; i++) {
        e[i] = (v[i] == 0.0f) ? 0.0f : __expf(v[i] - m);
        sum += e[i];
    }
    red[tid] = sum;
    __syncthreads();
#pragma unroll
    for (int s = 128; s > 0; s >>= 1) {
        if (tid < s) red[tid] += red[tid + s];
        __syncthreads();
    }
    const float inv = 1.0f / red[0];
#pragma unroll
    for (int i = 0; i < 8; i++) {
        __half h, l;
        split2(e[i] * inv, h, l);
        ph[tid + i * 256] = h;
        pl[tid + i * 256] = l;
    }
}

// ---------------- launch ----------------
extern "C" void kernel_launch(void* const* d_in, const int* in_sizes, int n_in,
                              void* d_out, int out_size) {
    (void)in_sizes; (void)n_in; (void)out_size;
    const float* Q = (const float*)d_in[0];
    const float* C = (const float*)d_in[1];
    const float* W = (const float*)d_in[2];
    const float* bias = (const float*)d_in[3];
    float* out = (float*)d_out;

    void *pScores, *pCombH, *pCombL, *pCH, *pCL, *pCTH, *pCTL, *pPH, *pPL, *pWH, *pWL;
    cudaGetSymbolAddress(&pScores, g_scores);
    cudaGetSymbolAddress(&pCombH, g_combH);
    cudaGetSymbolAddress(&pCombL, g_combL);
    cudaGetSymbolAddress(&pCH, g_cH);
    cudaGetSymbolAddress(&pCL, g_cL);
    cudaGetSymbolAddress(&pCTH, g_cTH);
    cudaGetSymbolAddress(&pCTL, g_cTL);
    cudaGetSymbolAddress(&pPH, g_PH);
    cudaGetSymbolAddress(&pPL, g_PL);
    cudaGetSymbolAddress(&pWH, g_WH);
    cudaGetSymbolAddress(&pWL, g_WL);

    cudaFuncSetAttribute((const void*)mma_gemm<0, 3>, cudaFuncAttributeMaxDynamicSharedMemorySize, SMEM_DYN);
    cudaFuncSetAttribute((const void*)mma_gemm<1, 2>, cudaFuncAttributeMaxDynamicSharedMemorySize, SMEM_DYN);
    cudaFuncSetAttribute((const void*)mma_gemm<2, 2>, cudaFuncAttributeMaxDynamicSharedMemorySize, SMEM_DYN);

    // conversions
    conv_q<<<(unsigned)((size_t)TT * BB * DD / 256), 256>>>(Q);
    conv_c_ct<<<dim3(DD / 32, SS / 32, BB), dim3(32, 8)>>>(C);
    conv_w<<<(unsigned)((size_t)DD * KK2 / 256), 256>>>(W);

    // GEMM1: scores = q . c   (fused 3-term)
    mma_gemm<0, 3><<<dim3(SS / 128, TT / 128, BB), 256, SMEM_DYN>>>(
        (const __half*)pCombH + DD, (const __half*)pCombL + DD,
        (size_t)KK2, (size_t)TT * KK2,
        (const __half*)pCH, (const __half*)pCL,
        (size_t)DD, (size_t)SS * DD,
        DD / 32,
        (float*)pScores, nullptr, nullptr, (size_t)SS, (size_t)TT * SS, nullptr);

    softmax_mask<<<BB * TT, 256>>>();

    // GEMM2: mix = P . cT   (fused 2-term) -> fp16 hi/lo into comb cols [0,1024)
    mma_gemm<1, 2><<<dim3(DD / 128, TT / 128, BB), 256, SMEM_DYN>>>(
        (const __half*)pPH, (const __half*)pPL,
        (size_t)SS, (size_t)TT * SS,
        (const __half*)pCTH, nullptr,
        (size_t)SS, (size_t)DD * SS,
        SS / 32,
        nullptr, (__half*)pCombH, (__half*)pCombL,
        (size_t)KK2, (size_t)TT * KK2, nullptr);

    // GEMM3: out = tanh(comb . W^T + bias)   (fused 2-term)
    mma_gemm<2, 2><<<dim3(DD / 128, TT / 128, BB), 256, SMEM_DYN>>>(
        (const __half*)pCombH, (const __half*)pCombL,
        (size_t)KK2, (size_t)TT * KK2,
        (const __half*)pWH, nullptr,
        (size_t)KK2, (size_t)0,
        KK2 / 32,
        out, nullptr, nullptr, (size_t)DD, (size_t)TT * DD, bias);
}

// round 6
// speedup vs baseline: 3.5682x; 1.0985x over previous
#include <cuda_runtime.h>
#include <cuda_fp16.h>
#include <math.h>
#include <stdint.h>

#define TT 2048
#define SS 2048
#define BB 16
#define DD 1024
#define KK2 2048

// ---------------- device scratch (static) ----------------
__device__ float  g_scores[(size_t)BB * TT * SS];   // 256 MiB
__device__ __half g_combH[(size_t)BB * TT * KK2];   // [b][t][0..1023]=mix, [1024..2047]=q
__device__ __half g_combL[(size_t)BB * TT * KK2];
__device__ __half g_cH[(size_t)BB * SS * DD];       // context hi [b][s][d]
__device__ __half g_cL[(size_t)BB * SS * DD];
__device__ __half g_cTH[(size_t)BB * DD * SS];      // context^T [b][d][s]
__device__ __half g_cTL[(size_t)BB * DD * SS];
__device__ __half g_PH[(size_t)BB * TT * SS];       // probs hi/lo
__device__ __half g_PL[(size_t)BB * TT * SS];
__device__ __half g_WH[(size_t)DD * KK2];
__device__ __half g_WL[(size_t)DD * KK2];

// ---------------- helpers ----------------
__device__ __forceinline__ void split2(float x, __half& h, __half& l) {
    h = __float2half_rn(x);
    l = __float2half_rn(x - __half2float(h));
}

__device__ __forceinline__ uint32_t smem_u32(const void* p) {
    uint32_t a;
    asm("{ .reg .u64 t; cvta.to.shared.u64 t, %1; cvt.u32.u64 %0, t; }" : "=r"(a) : "l"(p));
    return a;
}

__device__ __forceinline__ void ldsm4(uint32_t* r, uint32_t addr) {
    asm volatile("ldmatrix.sync.aligned.m8n8.x4.shared.b16 {%0,%1,%2,%3}, [%4];"
                 : "=r"(r[0]), "=r"(r[1]), "=r"(r[2]), "=r"(r[3]) : "r"(addr));
}

__device__ __forceinline__ void mma_f16(float* c, const uint32_t* a, uint32_t b0, uint32_t b1) {
    asm volatile(
        "mma.sync.aligned.m16n8k16.row.col.f32.f16.f16.f32 "
        "{%0,%1,%2,%3}, {%4,%5,%6,%7}, {%8,%9}, {%0,%1,%2,%3};"
        : "+f"(c[0]), "+f"(c[1]), "+f"(c[2]), "+f"(c[3])
        : "r"(a[0]), "r"(a[1]), "r"(a[2]), "r"(a[3]), "r"(b0), "r"(b1));
}

// 64B logical rows (K=32 fp16), 2 rows per 128B line, 8-sub XOR swizzle
__device__ __forceinline__ uint32_t sw_off(int r, int c16) {
    uint32_t line = (uint32_t)(r >> 1);
    uint32_t sub = (uint32_t)(c16 + ((r & 1) << 2));
    return (line << 7) + ((sub ^ (line & 7)) << 4);
}

// ---------------- fused split-precision fp16 mma.sync GEMM ----------------
// One K sweep; per 32-K chunk loads Ah, Al, Bh(, Bl) and accumulates:
//   NP=3: Ah*Bh + Al*Bh + Ah*Bl      NP=2: Ah*Bh + Al*Bh
// CTA tile M128 x N128, 8 warps (warp 32x64), cp.async ring, 2 CTAs/SM.
// EPI: 0=fp32 store, 1=fp16 hi/lo store, 2=bias+tanh fp32.
#define TILE_B 8192
#define SMEM_DYN 98304

template <int EPI, int NP>
__global__ __launch_bounds__(256, 2) void mma_gemm(
    const __half* __restrict__ Ah, const __half* __restrict__ Al,
    size_t a_row, size_t a_batch,
    const __half* __restrict__ Bh, const __half* __restrict__ Bl,
    size_t b_row, size_t b_batch,
    int KCH,  // K/32
    float* __restrict__ outF, __half* __restrict__ outH, __half* __restrict__ outL,
    size_t c_row, size_t c_batch, const float* __restrict__ bias) {
    constexpr int NT = (NP == 3) ? 4 : 3;       // tiles per stage
    constexpr int NSTG = (NP == 3) ? 3 : 4;     // ring depth (both = 96KB)
    constexpr uint32_t STAGE_B = NT * TILE_B;
    constexpr uint32_t AH_OFF = 0, AL_OFF = TILE_B, BH_OFF = 2 * TILE_B, BL_OFF = 3 * TILE_B;

    extern __shared__ char smem[];
    const uint32_t sb = smem_u32(smem);
    const int tid = threadIdx.x;
    const int lane = tid & 31, wid = tid >> 5;
    const int wm = wid & 3, wn = wid >> 2;  // 4x2 warp grid
    const int n0 = blockIdx.x * 128, m0 = blockIdx.y * 128, bz = blockIdx.z;

    const __half* A_h = Ah + (size_t)bz * a_batch + (size_t)m0 * a_row;
    const __half* A_l = Al + (size_t)bz * a_batch + (size_t)m0 * a_row;
    const __half* B_h = Bh + (size_t)bz * b_batch + (size_t)n0 * b_row;
    const __half* B_l = (NP == 3) ? (Bl + (size_t)bz * b_batch + (size_t)n0 * b_row) : nullptr;

    auto load_tile = [&](uint32_t dst, const __half* g, size_t rstride, int kk) {
#pragma unroll
        for (int i = tid; i < 512; i += 256) {
            const int r = i >> 2, cc = i & 3;
            const char* gp = (const char*)(g + (size_t)r * rstride + kk) + (cc << 4);
            asm volatile("cp.async.cg.shared.global [%0], [%1], 16;"
                         :: "r"(dst + sw_off(r, cc)), "l"(gp) : "memory");
        }
    };
    auto load_stage = [&](int c) {
        const int kk = c * 32;
        const uint32_t st = sb + (uint32_t)(c % NSTG) * STAGE_B;
        load_tile(st + AH_OFF, A_h, a_row, kk);
        load_tile(st + AL_OFF, A_l, a_row, kk);
        load_tile(st + BH_OFF, B_h, b_row, kk);
        if (NP == 3) load_tile(st + BL_OFF, B_l, b_row, kk);
        asm volatile("cp.async.commit_group;" ::: "memory");
    };

    // per-thread ldmatrix offsets within an 8KB tile (k16 step via XOR 0x20)
    uint32_t offA[2], offB[4];
    {
        const int gA = lane >> 4;
#pragma unroll
        for (int mi = 0; mi < 2; mi++)
            offA[mi] = sw_off(wm * 32 + mi * 16 + (lane & 15), gA);
        const int gB = (lane >> 3) & 1;
        const int rb = wn * 64 + ((lane >> 4) << 3) + (lane & 7);
#pragma unroll
        for (int nj = 0; nj < 4; nj++) offB[nj] = sw_off(rb + nj * 16, gB);
    }

    float acc[2][8][4];
#pragma unroll
    for (int i = 0; i < 2; i++)
#pragma unroll
        for (int j = 0; j < 8; j++)
#pragma unroll
            for (int q = 0; q < 4; q++) acc[i][j][q] = 0.0f;

#pragma unroll
    for (int s = 0; s < NSTG - 1; s++) load_stage(s);

    for (int c = 0; c < KCH; c++) {
        asm volatile("cp.async.wait_group %0;" :: "n"(NSTG - 2) : "memory");
        __syncthreads();
        if (c + NSTG - 1 < KCH) load_stage(c + NSTG - 1);
        else asm volatile("cp.async.commit_group;" ::: "memory");

        const uint32_t st = sb + (uint32_t)(c % NSTG) * STAGE_B;
#pragma unroll
        for (int k16 = 0; k16 < 2; k16++) {
            const uint32_t x = (uint32_t)(k16 << 5);
            uint32_t ah[2][4], al[2][4];
            ldsm4(ah[0], st + AH_OFF + (offA[0] ^ x));
            ldsm4(ah[1], st + AH_OFF + (offA[1] ^ x));
            ldsm4(al[0], st + AL_OFF + (offA[0] ^ x));
            ldsm4(al[1], st + AL_OFF + (offA[1] ^ x));
#pragma unroll
            for (int nj = 0; nj < 4; nj++) {
                uint32_t bh[4];
                ldsm4(bh, st + BH_OFF + (offB[nj] ^ x));
                mma_f16(acc[0][2 * nj], ah[0], bh[0], bh[1]);
                mma_f16(acc[0][2 * nj + 1], ah[0], bh[2], bh[3]);
                mma_f16(acc[1][2 * nj], ah[1], bh[0], bh[1]);
                mma_f16(acc[1][2 * nj + 1], ah[1], bh[2], bh[3]);
                mma_f16(acc[0][2 * nj], al[0], bh[0], bh[1]);
                mma_f16(acc[0][2 * nj + 1], al[0], bh[2], bh[3]);
                mma_f16(acc[1][2 * nj], al[1], bh[0], bh[1]);
                mma_f16(acc[1][2 * nj + 1], al[1], bh[2], bh[3]);
                if (NP == 3) {
                    uint32_t bl[4];
                    ldsm4(bl, st + BL_OFF + (offB[nj] ^ x));
                    mma_f16(acc[0][2 * nj], ah[0], bl[0], bl[1]);
                    mma_f16(acc[0][2 * nj + 1], ah[0], bl[2], bl[3]);
                    mma_f16(acc[1][2 * nj], ah[1], bl[0], bl[1]);
                    mma_f16(acc[1][2 * nj + 1], ah[1], bl[2], bl[3]);
                }
            }
        }
    }

    // -------- epilogue --------
    const int trow = lane >> 2, tcol = (lane & 3) * 2;
#pragma unroll
    for (int mi = 0; mi < 2; mi++) {
#pragma unroll
        for (int nj = 0; nj < 8; nj++) {
            const int row = m0 + wm * 32 + mi * 16 + trow;
            const int col = n0 + wn * 64 + nj * 8 + tcol;
            const float* a4 = acc[mi][nj];
            if (EPI == 0) {
                float* p = outF + (size_t)bz * c_batch + (size_t)row * c_row + col;
                *(float2*)p = make_float2(a4[0], a4[1]);
                *(float2*)(p + 8 * c_row) = make_float2(a4[2], a4[3]);
            } else if (EPI == 1) {
                __half* ph = outH + (size_t)bz * c_batch + (size_t)row * c_row + col;
                __half* pl = outL + (size_t)bz * c_batch + (size_t)row * c_row + col;
                __half h0, l0, h1, l1;
                split2(a4[0], h0, l0);
                split2(a4[1], h1, l1);
                __half2 vh, vl;
                vh.x = h0; vh.y = h1; vl.x = l0; vl.y = l1;
                *(__half2*)ph = vh;
                *(__half2*)pl = vl;
                split2(a4[2], h0, l0);
                split2(a4[3], h1, l1);
                vh.x = h0; vh.y = h1; vl.x = l0; vl.y = l1;
                *(__half2*)(ph + 8 * c_row) = vh;
                *(__half2*)(pl + 8 * c_row) = vl;
            } else {
                const float b0 = bias[col], b1 = bias[col + 1];
                float* p = outF + (size_t)bz * c_batch + (size_t)row * c_row + col;
                *(float2*)p = make_float2(tanhf(a4[0] + b0), tanhf(a4[1] + b1));
                *(float2*)(p + 8 * c_row) = make_float2(tanhf(a4[2] + b0), tanhf(a4[3] + b1));
            }
        }
    }
}

// ---------------- conversion kernels (vectorized) ----------------
__global__ __launch_bounds__(256) void conv_q(const float* __restrict__ Q) {
    size_t i4 = ((size_t)blockIdx.x * 256 + threadIdx.x) * 4;  // over T*B*D
    float4 v = *(const float4*)(Q + i4);
    int d = (int)(i4 & (DD - 1));
    size_t j = i4 >> 10;
    int b = (int)(j & (BB - 1));
    size_t t = j >> 4;
    size_t o = ((size_t)b * TT + t) * KK2 + DD + d;
    __half h0, l0, h1, l1;
    __half2 vh, vl;
    split2(v.x, h0, l0); split2(v.y, h1, l1);
    vh.x = h0; vh.y = h1; vl.x = l0; vl.y = l1;
    *(__half2*)(g_combH + o) = vh;
    *(__half2*)(g_combL + o) = vl;
    split2(v.z, h0, l0); split2(v.w, h1, l1);
    vh.x = h0; vh.y = h1; vl.x = l0; vl.y = l1;
    *(__half2*)(g_combH + o + 2) = vh;
    *(__half2*)(g_combL + o + 2) = vl;
}

__global__ __launch_bounds__(256) void conv_c_ct(const float* __restrict__ C) {
    __shared__ float tile[32][33];
    const int b = blockIdx.z;
    const int d0 = blockIdx.x * 32, s0 = blockIdx.y * 32;
    const int tx = threadIdx.x, ty = threadIdx.y;  // (32,8)
#pragma unroll
    for (int i = 0; i < 4; i++) {
        int s = s0 + ty + i * 8;
        float v = C[((size_t)s * BB + b) * DD + d0 + tx];
        tile[ty + i * 8][tx] = v;
        __half h, l;
        split2(v, h, l);
        size_t o = ((size_t)b * SS + s) * DD + d0 + tx;
        g_cH[o] = h;
        g_cL[o] = l;
    }
    __syncthreads();
#pragma unroll
    for (int i = 0; i < 4; i++) {
        int d = d0 + ty + i * 8;
        __half h, l;
        split2(tile[tx][ty + i * 8], h, l);
        size_t o = ((size_t)b * DD + d) * SS + s0 + tx;
        g_cTH[o] = h;
        g_cTL[o] = l;
    }
}

__global__ __launch_bounds__(256) void conv_w(const float* __restrict__ W) {
    size_t i4 = ((size_t)blockIdx.x * 256 + threadIdx.x) * 4;  // over D*2D
    float4 v = *(const float4*)(W + i4);
    __half h0, l0, h1, l1;
    __half2 vh, vl;
    split2(v.x, h0, l0); split2(v.y, h1, l1);
    vh.x = h0; vh.y = h1; vl.x = l0; vl.y = l1;
    *(__half2*)(g_WH + i4) = vh;
    *(__half2*)(g_WL + i4) = vl;
    split2(v.z, h0, l0); split2(v.w, h1, l1);
    vh.x = h0; vh.y = h1; vl.x = l0; vl.y = l1;
    *(__half2*)(g_WH + i4 + 2) = vh;
    *(__half2*)(g_WL + i4 + 2) = vl;
}

// ---------------- softmax (==0 -> -inf mask), fp32 scores -> fp16 hi/lo probs ----------------
__global__ __launch_bounds__(256) void softmax_mask() {
    const size_t rowi = blockIdx.x;
    const float* p = g_scores + rowi * SS;
    __half* ph = g_PH + rowi * SS;
    __half* pl = g_PL + rowi * SS;
    const int tid = threadIdx.x;
    __shared__ float red[256];
    float v[8];
    float m = -INFINITY;
#pragma unroll
    for (int i = 0; i < 8; i++) {
        v[i] = p[tid + i * 256];
        float x = (v[i] == 0.0f) ? -INFINITY : v[i];
        m = fmaxf(m, x);
    }
    red[tid] = m;
    __syncthreads();
#pragma unroll
    for (int s = 128; s > 0; s >>= 1) {
        if (tid < s) red[tid] = fmaxf(red[tid], red[tid + s]);
        __syncthreads();
    }
    m = red[0];
    __syncthreads();
    float e[8];
    float sum = 0.0f;
#pragma unroll
    for (int i = 0; i < 8; i++) {
        e[i] = (v[i] == 0.0f) ? 0.0f : __expf(v[i] - m);
        sum += e[i];
    }
    red[tid] = sum;
    __syncthreads();
#pragma unroll
    for (int s = 128; s > 0; s >>= 1) {
        if (tid < s) red[tid] += red[tid + s];
        __syncthreads();
    }
    const float inv = 1.0f / red[0];
#pragma unroll
    for (int i = 0; i < 8; i++) {
        __half h, l;
        split2(e[i] * inv, h, l);
        ph[tid + i * 256] = h;
        pl[tid + i * 256] = l;
    }
}

// ---------------- launch ----------------
extern "C" void kernel_launch(void* const* d_in, const int* in_sizes, int n_in,
                              void* d_out, int out_size) {
    (void)in_sizes; (void)n_in; (void)out_size;
    const float* Q = (const float*)d_in[0];
    const float* C = (const float*)d_in[1];
    const float* W = (const float*)d_in[2];
    const float* bias = (const float*)d_in[3];
    float* out = (float*)d_out;

    void *pScores, *pCombH, *pCombL, *pCH, *pCL, *pCTH, *pCTL, *pPH, *pPL, *pWH, *pWL;
    cudaGetSymbolAddress(&pScores, g_scores);
    cudaGetSymbolAddress(&pCombH, g_combH);
    cudaGetSymbolAddress(&pCombL, g_combL);
    cudaGetSymbolAddress(&pCH, g_cH);
    cudaGetSymbolAddress(&pCL, g_cL);
    cudaGetSymbolAddress(&pCTH, g_cTH);
    cudaGetSymbolAddress(&pCTL, g_cTL);
    cudaGetSymbolAddress(&pPH, g_PH);
    cudaGetSymbolAddress(&pPL, g_PL);
    cudaGetSymbolAddress(&pWH, g_WH);
    cudaGetSymbolAddress(&pWL, g_WL);

    cudaFuncSetAttribute((const void*)mma_gemm<0, 3>, cudaFuncAttributeMaxDynamicSharedMemorySize, SMEM_DYN);
    cudaFuncSetAttribute((const void*)mma_gemm<1, 2>, cudaFuncAttributeMaxDynamicSharedMemorySize, SMEM_DYN);
    cudaFuncSetAttribute((const void*)mma_gemm<2, 2>, cudaFuncAttributeMaxDynamicSharedMemorySize, SMEM_DYN);

    // conversions
    conv_q<<<(unsigned)((size_t)TT * BB * DD / 1024), 256>>>(Q);
    conv_c_ct<<<dim3(DD / 32, SS / 32, BB), dim3(32, 8)>>>(C);
    conv_w<<<(unsigned)((size_t)DD * KK2 / 1024), 256>>>(W);

    // GEMM1: scores = q . c   (fused 3-term)
    mma_gemm<0, 3><<<dim3(SS / 128, TT / 128, BB), 256, SMEM_DYN>>>(
        (const __half*)pCombH + DD, (const __half*)pCombL + DD,
        (size_t)KK2, (size_t)TT * KK2,
        (const __half*)pCH, (const __half*)pCL,
        (size_t)DD, (size_t)SS * DD,
        DD / 32,
        (float*)pScores, nullptr, nullptr, (size_t)SS, (size_t)TT * SS, nullptr);

    softmax_mask<<<BB * TT, 256>>>();

    // GEMM2: mix = P . cT   (fused 2-term) -> fp16 hi/lo into comb cols [0,1024)
    mma_gemm<1, 2><<<dim3(DD / 128, TT / 128, BB), 256, SMEM_DYN>>>(
        (const __half*)pPH, (const __half*)pPL,
        (size_t)SS, (size_t)TT * SS,
        (const __half*)pCTH, nullptr,
        (size_t)SS, (size_t)DD * SS,
        SS / 32,
        nullptr, (__half*)pCombH, (__half*)pCombL,
        (size_t)KK2, (size_t)TT * KK2, nullptr);

    // GEMM3: out = tanh(comb . W^T + bias)   (fused 2-term)
    mma_gemm<2, 2><<<dim3(DD / 128, TT / 128, BB), 256, SMEM_DYN>>>(
        (const __half*)pCombH, (const __half*)pCombL,
        (size_t)KK2, (size_t)TT * KK2,
        (const __half*)pWH, nullptr,
        (size_t)KK2, (size_t)0,
        KK2 / 32,
        out, nullptr, nullptr, (size_t)DD, (size_t)TT * DD, bias);
}